// round 7
// baseline (speedup 1.0000x reference)
#include <cuda_runtime.h>
#include <cuda_bf16.h>
#include <cstdint>

// Shapes
#define B_   128
#define L_   1024
#define RNN_ 1024
#define ATT_ 512
#define KSPLIT 8   // k-split for K1
#define NCHUNK 8   // chunks of the compacted list for K2/K4

// Scratch (device globals — allocation-free)
__device__ __align__(16) float g_atth_part[KSPLIT][B_ * ATT_];   // 2 MB
__device__ __align__(16) float g_cdot[B_ * L_];                  // dot at compacted pos
__device__ __align__(16) float g_part[NCHUNK][B_ * RNN_];        // 4 MB partials
__device__ int g_sem[B_];                                        // zero-init; reset by combiner

__device__ __forceinline__ float tanh_fast(float x) {
    float y;
    asm("tanh.approx.f32 %0, %1;" : "=f"(y) : "f"(x));
    return y;
}

// In-block order-preserving compaction of one mask row (1024 entries, 256 thr).
__device__ __forceinline__ int compact_inblock(const float* __restrict__ m, int* sidx) {
    __shared__ int wcnt[8], woff[8];
    const int tid = threadIdx.x;
    const int warp = tid >> 5;
    const int lane = tid & 31;

    unsigned bms[4];
    int cnt = 0;
#pragma unroll
    for (int it = 0; it < 4; it++) {
        const int l = warp * 128 + it * 32 + lane;
        bms[it] = __ballot_sync(0xffffffffu, m[l] != 0.f);
        cnt += __popc(bms[it]);
    }
    if (lane == 0) wcnt[warp] = cnt;
    __syncthreads();
    if (tid == 0) {
        int r = 0;
#pragma unroll
        for (int i = 0; i < 8; i++) { woff[i] = r; r += wcnt[i]; }
        wcnt[0] = r;
    }
    __syncthreads();
    int off = woff[warp];
#pragma unroll
    for (int it = 0; it < 4; it++) {
        const int l = warp * 128 + it * 32 + lane;
        const unsigned bm = bms[it];
        if (bm & (1u << lane))
            sidx[off + __popc(bm & ((1u << lane) - 1u))] = l;
        off += __popc(bm);
    }
    const int total = wcnt[0];
    __syncthreads();
    return total;
}

// ------------------------------------------------------------------
// K1: att_h partials = h[128,1024] @ W[512,1024]^T, 64x64 tiles, ksplit=8
// ------------------------------------------------------------------
__global__ void k1_gemm(const float* __restrict__ h, const float* __restrict__ W) {
    __shared__ float Hs[64][17];
    __shared__ float Ws[64][17];
    const int a0 = blockIdx.x * 64;
    const int b0 = blockIdx.y * 64;
    const int k0 = blockIdx.z * (RNN_ / KSPLIT);
    const int tid = threadIdx.x;
    const int tx = tid & 15;
    const int ty = tid >> 4;
    const int lr = tid >> 2;
    const int lc = (tid & 3) * 4;

    float c[4][4];
#pragma unroll
    for (int i = 0; i < 4; i++)
#pragma unroll
        for (int j = 0; j < 4; j++) c[i][j] = 0.f;

    for (int kk = 0; kk < RNN_ / KSPLIT; kk += 16) {
        float4 hv = *(const float4*)(h + (size_t)(b0 + lr) * RNN_ + k0 + kk + lc);
        float4 wv = *(const float4*)(W + (size_t)(a0 + lr) * RNN_ + k0 + kk + lc);
        Hs[lr][lc] = hv.x; Hs[lr][lc + 1] = hv.y; Hs[lr][lc + 2] = hv.z; Hs[lr][lc + 3] = hv.w;
        Ws[lr][lc] = wv.x; Ws[lr][lc + 1] = wv.y; Ws[lr][lc + 2] = wv.z; Ws[lr][lc + 3] = wv.w;
        __syncthreads();
#pragma unroll
        for (int k = 0; k < 16; k++) {
            float hr[4], wr[4];
#pragma unroll
            for (int i = 0; i < 4; i++) hr[i] = Hs[ty * 4 + i][k];
#pragma unroll
            for (int j = 0; j < 4; j++) wr[j] = Ws[tx * 4 + j][k];
#pragma unroll
            for (int i = 0; i < 4; i++)
#pragma unroll
                for (int j = 0; j < 4; j++) c[i][j] += hr[i] * wr[j];
        }
        __syncthreads();
    }
#pragma unroll
    for (int i = 0; i < 4; i++)
#pragma unroll
        for (int j = 0; j < 4; j++)
            g_atth_part[blockIdx.z][(b0 + ty * 4 + i) * ATT_ + a0 + tx * 4 + j] = c[i][j];
}

// ------------------------------------------------------------------
// K2: cdot[b,j] = sum_a tanh(f2[b,cidx[j],a] + att_h[b,a]) * w_alpha[a] + b_alpha
// ------------------------------------------------------------------
__global__ void k2_dot(const float* __restrict__ f2,
                       const float* __restrict__ mask,
                       const float* __restrict__ w_alpha,
                       const float* __restrict__ b_h2att,
                       const float* __restrict__ b_alpha) {
    __shared__ __align__(16) float atth[ATT_];
    __shared__ __align__(16) float wal[ATT_];
    __shared__ int sidx[L_];
    const int b  = blockIdx.x;
    const int ch = blockIdx.y;
    const int tid = threadIdx.x;

    const int cnt = compact_inblock(mask + (size_t)b * L_, sidx);

    for (int i = tid; i < ATT_; i += 256) {
        float s = b_h2att[i];
#pragma unroll
        for (int p = 0; p < KSPLIT; p++) s += g_atth_part[p][b * ATT_ + i];
        atth[i] = s;
        wal[i] = w_alpha[i];
    }
    __syncthreads();

    const int warp = tid >> 5;
    const int lane = tid & 31;
    float4 ah[4], wa[4];
#pragma unroll
    for (int j = 0; j < 4; j++) {
        ah[j] = ((const float4*)atth)[lane + 32 * j];
        wa[j] = ((const float4*)wal)[lane + 32 * j];
    }
    const float balpha = *b_alpha;
    const int chunk = (cnt + NCHUNK - 1) / NCHUNK;
    const int start = ch * chunk;
    const int end = min(start + chunk, cnt);
    const float* fb = f2 + (size_t)b * L_ * ATT_;

    for (int j = start + warp; j < end; j += 8) {
        const int li = sidx[j];
        const float4* row = (const float4*)(fb + (size_t)li * ATT_);
        float s = 0.f;
#pragma unroll
        for (int q = 0; q < 4; q++) {
            float4 v = row[lane + 32 * q];
            s += tanh_fast(v.x + ah[q].x) * wa[q].x;
            s += tanh_fast(v.y + ah[q].y) * wa[q].y;
            s += tanh_fast(v.z + ah[q].z) * wa[q].z;
            s += tanh_fast(v.w + ah[q].w) * wa[q].w;
        }
#pragma unroll
        for (int o = 16; o; o >>= 1) s += __shfl_xor_sync(0xffffffffu, s, o);
        if (lane == 0) g_cdot[b * L_ + j] = s + balpha;
    }
}

// ------------------------------------------------------------------
// K4: fused softmax-normalize + weighted gather + last-block combine.
// Release protocol (per WRITER thread): st(partial) -> __threadfence()
//   -> __syncthreads()  [tid0 cannot signal until EVERY thread has fenced
//      its own store — this was the round-5/6 race] -> tid0 atomicAdd(sem).
// Acquire protocol (combiner): observe prev==7 -> __threadfence() ->
//   __ldcg partial loads (L2-coherent). Fixed c-order sum = deterministic.
// ------------------------------------------------------------------
__global__ void k4_weighted(const float* __restrict__ f1,
                            const float* __restrict__ mask,
                            float* __restrict__ out) {
    __shared__ int sidx[L_];
    __shared__ float sw[(L_ / NCHUNK) + NCHUNK];
    __shared__ float red[8];
    __shared__ float stat;
    __shared__ int is_last;
    const int b = blockIdx.x;
    const int c = blockIdx.y;
    const int tid = threadIdx.x;
    const int warp = tid >> 5;
    const int lane = tid & 31;

    const int cnt = compact_inblock(mask + (size_t)b * L_, sidx);

    // --- block softmax stats over g_cdot[b, 0..cnt) ---
    float mx = -1e30f;
    for (int j = tid; j < cnt; j += 256) mx = fmaxf(mx, g_cdot[b * L_ + j]);
#pragma unroll
    for (int o = 16; o; o >>= 1) mx = fmaxf(mx, __shfl_xor_sync(0xffffffffu, mx, o));
    if (lane == 0) red[warp] = mx;
    __syncthreads();
    if (tid < 8) {
        float v = red[tid];
#pragma unroll
        for (int o = 4; o; o >>= 1) v = fmaxf(v, __shfl_xor_sync(0xffu, v, o));
        if (tid == 0) stat = v;
    }
    __syncthreads();
    const float bmax = stat;

    float s = 0.f;
    for (int j = tid; j < cnt; j += 256) s += __expf(g_cdot[b * L_ + j] - bmax);
#pragma unroll
    for (int o = 16; o; o >>= 1) s += __shfl_xor_sync(0xffffffffu, s, o);
    __syncthreads();
    if (lane == 0) red[warp] = s;
    __syncthreads();
    if (tid < 8) {
        float v = red[tid];
#pragma unroll
        for (int o = 4; o; o >>= 1) v += __shfl_xor_sync(0xffu, v, o);
        if (tid == 0) stat = v;
    }
    __syncthreads();
    const float inv = 1.0f / stat;

    // --- own chunk weights ---
    const int chunk = (cnt + NCHUNK - 1) / NCHUNK;
    const int start = c * chunk;
    const int end = min(start + chunk, cnt);
    const int n = max(end - start, 0);
    for (int i = tid; i < n; i += 256)
        sw[i] = __expf(g_cdot[b * L_ + start + i] - bmax) * inv;
    __syncthreads();

    // --- gather-accumulate ---
    const float4* fb = (const float4*)(f1 + (size_t)b * L_ * RNN_) + tid;
    float4 acc = make_float4(0.f, 0.f, 0.f, 0.f);
#pragma unroll 8
    for (int i = 0; i < n; i++) {
        const float w = sw[i];
        float4 v = fb[(size_t)sidx[start + i] * (RNN_ / 4)];
        acc.x += w * v.x;
        acc.y += w * v.y;
        acc.z += w * v.z;
        acc.w += w * v.w;
    }
    ((float4*)(g_part[c] + b * RNN_))[tid] = acc;

    // --- release: every thread fences ITS OWN store, then barrier, then signal ---
    __threadfence();
    __syncthreads();
    if (tid == 0) {
        int prev = atomicAdd(&g_sem[b], 1);
        is_last = (prev == NCHUNK - 1);
    }
    __syncthreads();

    // --- acquire + combine (one block per b wins; fixed order => deterministic) ---
    if (is_last) {
        __threadfence();
        float4 a = make_float4(0.f, 0.f, 0.f, 0.f);
#pragma unroll
        for (int q = 0; q < NCHUNK; q++) {
            float4 v = __ldcg((const float4*)(g_part[q] + b * RNN_) + tid);
            a.x += v.x; a.y += v.y; a.z += v.z; a.w += v.w;
        }
        ((float4*)(out + (size_t)b * RNN_))[tid] = a;
        __threadfence();
        if (tid == 0) g_sem[b] = 0;        // reset for next graph replay
    }
}

extern "C" void kernel_launch(void* const* d_in, const int* in_sizes, int n_in,
                              void* d_out, int out_size) {
    const float* h    = (const float*)d_in[0];
    const float* f1   = (const float*)d_in[1];  // att_feats1 [128,1024,1024]
    const float* f2   = (const float*)d_in[2];  // att_feats2 [128,1024,512]
    const float* mask = (const float*)d_in[3];
    const float* W    = (const float*)d_in[4];  // [512,1024]
    const float* bh   = (const float*)d_in[5];  // [512]
    const float* wal  = (const float*)d_in[6];  // [512]
    const float* bal  = (const float*)d_in[7];  // scalar
    float* out = (float*)d_out;

    k1_gemm<<<dim3(ATT_ / 64, B_ / 64, KSPLIT), 256>>>(h, W);
    k2_dot<<<dim3(B_, NCHUNK), 256>>>(f2, mask, wal, bh, bal);
    k4_weighted<<<dim3(B_, NCHUNK), 256>>>(f1, mask, out);
}

// round 8
// speedup vs baseline: 1.0051x; 1.0051x over previous
#include <cuda_runtime.h>
#include <cuda_bf16.h>
#include <cstdint>

// Shapes
#define B_   128
#define L_   1024
#define RNN_ 1024
#define ATT_ 512
#define KSPLIT 32  // k-split for K1 (512 blocks -> fills the chip)
#define NCHUNK 8   // chunks of the compacted list for K2/K4

// Scratch (device globals — allocation-free)
__device__ __align__(16) float g_atth_part[KSPLIT][B_ * ATT_];   // 8 MB
__device__ __align__(16) float g_cdot[B_ * L_];                  // dot at compacted pos
__device__ __align__(16) float g_part[NCHUNK][B_ * RNN_];        // 4 MB partials

__device__ __forceinline__ float tanh_fast(float x) {
    float y;
    asm("tanh.approx.f32 %0, %1;" : "=f"(y) : "f"(x));
    return y;
}

// In-block order-preserving compaction of one mask row (1024 entries, 256 thr).
__device__ __forceinline__ int compact_inblock(const float* __restrict__ m, int* sidx) {
    __shared__ int wcnt[8], woff[8];
    const int tid = threadIdx.x;
    const int warp = tid >> 5;
    const int lane = tid & 31;

    unsigned bms[4];
    int cnt = 0;
#pragma unroll
    for (int it = 0; it < 4; it++) {
        const int l = warp * 128 + it * 32 + lane;
        bms[it] = __ballot_sync(0xffffffffu, m[l] != 0.f);
        cnt += __popc(bms[it]);
    }
    if (lane == 0) wcnt[warp] = cnt;
    __syncthreads();
    if (tid == 0) {
        int r = 0;
#pragma unroll
        for (int i = 0; i < 8; i++) { woff[i] = r; r += wcnt[i]; }
        wcnt[0] = r;
    }
    __syncthreads();
    int off = woff[warp];
#pragma unroll
    for (int it = 0; it < 4; it++) {
        const int l = warp * 128 + it * 32 + lane;
        const unsigned bm = bms[it];
        if (bm & (1u << lane))
            sidx[off + __popc(bm & ((1u << lane) - 1u))] = l;
        off += __popc(bm);
    }
    const int total = wcnt[0];
    __syncthreads();
    return total;
}

// ------------------------------------------------------------------
// K1: att_h partials = h[128,1024] @ W[512,1024]^T
// 64x64 tiles, KSPLIT=32 -> grid 512 blocks (K=32 slice per block).
// ------------------------------------------------------------------
__global__ void k1_gemm(const float* __restrict__ h, const float* __restrict__ W) {
    __shared__ float Hs[64][17];
    __shared__ float Ws[64][17];
    const int a0 = blockIdx.x * 64;
    const int b0 = blockIdx.y * 64;
    const int k0 = blockIdx.z * (RNN_ / KSPLIT);  // 32-wide k range
    const int tid = threadIdx.x;
    const int tx = tid & 15;
    const int ty = tid >> 4;
    const int lr = tid >> 2;
    const int lc = (tid & 3) * 4;

    float c[4][4];
#pragma unroll
    for (int i = 0; i < 4; i++)
#pragma unroll
        for (int j = 0; j < 4; j++) c[i][j] = 0.f;

#pragma unroll
    for (int kk = 0; kk < RNN_ / KSPLIT; kk += 16) {
        float4 hv = *(const float4*)(h + (size_t)(b0 + lr) * RNN_ + k0 + kk + lc);
        float4 wv = *(const float4*)(W + (size_t)(a0 + lr) * RNN_ + k0 + kk + lc);
        Hs[lr][lc] = hv.x; Hs[lr][lc + 1] = hv.y; Hs[lr][lc + 2] = hv.z; Hs[lr][lc + 3] = hv.w;
        Ws[lr][lc] = wv.x; Ws[lr][lc + 1] = wv.y; Ws[lr][lc + 2] = wv.z; Ws[lr][lc + 3] = wv.w;
        __syncthreads();
#pragma unroll
        for (int k = 0; k < 16; k++) {
            float hr[4], wr[4];
#pragma unroll
            for (int i = 0; i < 4; i++) hr[i] = Hs[ty * 4 + i][k];
#pragma unroll
            for (int j = 0; j < 4; j++) wr[j] = Ws[tx * 4 + j][k];
#pragma unroll
            for (int i = 0; i < 4; i++)
#pragma unroll
                for (int j = 0; j < 4; j++) c[i][j] += hr[i] * wr[j];
        }
        __syncthreads();
    }
#pragma unroll
    for (int i = 0; i < 4; i++)
#pragma unroll
        for (int j = 0; j < 4; j++)
            g_atth_part[blockIdx.z][(b0 + ty * 4 + i) * ATT_ + a0 + tx * 4 + j] = c[i][j];
}

// ------------------------------------------------------------------
// K2: cdot[b,j] = sum_a tanh(f2[b,cidx[j],a] + att_h[b,a]) * w_alpha[a] + b_alpha
// ------------------------------------------------------------------
__global__ void k2_dot(const float* __restrict__ f2,
                       const float* __restrict__ mask,
                       const float* __restrict__ w_alpha,
                       const float* __restrict__ b_h2att,
                       const float* __restrict__ b_alpha) {
    __shared__ __align__(16) float atth[ATT_];
    __shared__ __align__(16) float wal[ATT_];
    __shared__ int sidx[L_];
    const int b  = blockIdx.x;
    const int ch = blockIdx.y;
    const int tid = threadIdx.x;

    const int cnt = compact_inblock(mask + (size_t)b * L_, sidx);

    for (int i = tid; i < ATT_; i += 256) {
        float s = b_h2att[i];
#pragma unroll
        for (int p = 0; p < KSPLIT; p++) s += g_atth_part[p][b * ATT_ + i];
        atth[i] = s;
        wal[i] = w_alpha[i];
    }
    __syncthreads();

    const int warp = tid >> 5;
    const int lane = tid & 31;
    float4 ah[4], wa[4];
#pragma unroll
    for (int j = 0; j < 4; j++) {
        ah[j] = ((const float4*)atth)[lane + 32 * j];
        wa[j] = ((const float4*)wal)[lane + 32 * j];
    }
    const float balpha = *b_alpha;
    const int chunk = (cnt + NCHUNK - 1) / NCHUNK;
    const int start = ch * chunk;
    const int end = min(start + chunk, cnt);
    const float* fb = f2 + (size_t)b * L_ * ATT_;

    for (int j = start + warp; j < end; j += 8) {
        const int li = sidx[j];
        const float4* row = (const float4*)(fb + (size_t)li * ATT_);
        float s = 0.f;
#pragma unroll
        for (int q = 0; q < 4; q++) {
            float4 v = row[lane + 32 * q];
            s += tanh_fast(v.x + ah[q].x) * wa[q].x;
            s += tanh_fast(v.y + ah[q].y) * wa[q].y;
            s += tanh_fast(v.z + ah[q].z) * wa[q].z;
            s += tanh_fast(v.w + ah[q].w) * wa[q].w;
        }
#pragma unroll
        for (int o = 16; o; o >>= 1) s += __shfl_xor_sync(0xffffffffu, s, o);
        if (lane == 0) g_cdot[b * L_ + j] = s + balpha;
    }
}

// ------------------------------------------------------------------
// K4: fused softmax normalization + weighted gather -> partials.
// (No cross-block sync: combine is k5's job — measured faster than
//  the in-kernel fence/semaphore variant.)
// ------------------------------------------------------------------
__global__ void k4_weighted(const float* __restrict__ f1,
                            const float* __restrict__ mask) {
    __shared__ int sidx[L_];
    __shared__ float sw[(L_ / NCHUNK) + NCHUNK];
    __shared__ float red[8];
    __shared__ float stat;
    const int b = blockIdx.x;
    const int c = blockIdx.y;
    const int tid = threadIdx.x;
    const int warp = tid >> 5;
    const int lane = tid & 31;

    const int cnt = compact_inblock(mask + (size_t)b * L_, sidx);

    // --- block softmax stats over g_cdot[b, 0..cnt) ---
    float mx = -1e30f;
    for (int j = tid; j < cnt; j += 256) mx = fmaxf(mx, g_cdot[b * L_ + j]);
#pragma unroll
    for (int o = 16; o; o >>= 1) mx = fmaxf(mx, __shfl_xor_sync(0xffffffffu, mx, o));
    if (lane == 0) red[warp] = mx;
    __syncthreads();
    if (tid < 8) {
        float v = red[tid];
#pragma unroll
        for (int o = 4; o; o >>= 1) v = fmaxf(v, __shfl_xor_sync(0xffu, v, o));
        if (tid == 0) stat = v;
    }
    __syncthreads();
    const float bmax = stat;

    float s = 0.f;
    for (int j = tid; j < cnt; j += 256) s += __expf(g_cdot[b * L_ + j] - bmax);
#pragma unroll
    for (int o = 16; o; o >>= 1) s += __shfl_xor_sync(0xffffffffu, s, o);
    __syncthreads();
    if (lane == 0) red[warp] = s;
    __syncthreads();
    if (tid < 8) {
        float v = red[tid];
#pragma unroll
        for (int o = 4; o; o >>= 1) v += __shfl_xor_sync(0xffu, v, o);
        if (tid == 0) stat = v;
    }
    __syncthreads();
    const float inv = 1.0f / stat;

    // --- own chunk weights ---
    const int chunk = (cnt + NCHUNK - 1) / NCHUNK;
    const int start = c * chunk;
    const int end = min(start + chunk, cnt);
    const int n = max(end - start, 0);
    for (int i = tid; i < n; i += 256)
        sw[i] = __expf(g_cdot[b * L_ + start + i] - bmax) * inv;
    __syncthreads();

    // --- gather-accumulate ---
    const float4* fb = (const float4*)(f1 + (size_t)b * L_ * RNN_) + tid;
    float4 acc = make_float4(0.f, 0.f, 0.f, 0.f);
#pragma unroll 8
    for (int i = 0; i < n; i++) {
        const float w = sw[i];
        float4 v = fb[(size_t)sidx[start + i] * (RNN_ / 4)];
        acc.x += w * v.x;
        acc.y += w * v.y;
        acc.z += w * v.z;
        acc.w += w * v.w;
    }
    ((float4*)(g_part[c] + b * RNN_))[tid] = acc;
}

// ------------------------------------------------------------------
// K5: out[b,d] = sum_c partial[c][b,d] — wide grid (256 blocks x 128 thr,
// one float4 out + 8 independent loads per thread) for latency hiding.
// ------------------------------------------------------------------
__global__ void k5_combine(float* __restrict__ out) {
    const int i = blockIdx.x * 128 + threadIdx.x;  // float4 index, 32768 total
    float4 a = make_float4(0.f, 0.f, 0.f, 0.f);
#pragma unroll
    for (int c = 0; c < NCHUNK; c++) {
        float4 v = ((const float4*)g_part)[(size_t)c * (B_ * RNN_ / 4) + i];
        a.x += v.x; a.y += v.y; a.z += v.z; a.w += v.w;
    }
    ((float4*)out)[i] = a;
}

extern "C" void kernel_launch(void* const* d_in, const int* in_sizes, int n_in,
                              void* d_out, int out_size) {
    const float* h    = (const float*)d_in[0];
    const float* f1   = (const float*)d_in[1];  // att_feats1 [128,1024,1024]
    const float* f2   = (const float*)d_in[2];  // att_feats2 [128,1024,512]
    const float* mask = (const float*)d_in[3];
    const float* W    = (const float*)d_in[4];  // [512,1024]
    const float* bh   = (const float*)d_in[5];  // [512]
    const float* wal  = (const float*)d_in[6];  // [512]
    const float* bal  = (const float*)d_in[7];  // scalar
    float* out = (float*)d_out;

    k1_gemm<<<dim3(ATT_ / 64, B_ / 64, KSPLIT), 256>>>(h, W);
    k2_dot<<<dim3(B_, NCHUNK), 256>>>(f2, mask, wal, bh, bal);
    k4_weighted<<<dim3(B_, NCHUNK), 256>>>(f1, mask);
    k5_combine<<<(B_ * RNN_ / 4) / 128, 128>>>(out);
}